// round 1
// baseline (speedup 1.0000x reference)
#include <cuda_runtime.h>

#define SEQ 20
#define DK  64
#define BHB 2        // (b,h) problems per block
#define THREADS 256

#define QS 65        // Q,K smem row stride (conflict-free scalar reads)
#define VS 68        // V smem row stride (float4-aligned, 17 float4/row)
#define WS 21        // scores/W smem row stride

__global__ __launch_bounds__(THREADS)
void sdpa_rel_kernel(const float* __restrict__ Qg,
                     const float* __restrict__ Kg,
                     const float* __restrict__ Vg,
                     const float* __restrict__ Mg,
                     float* __restrict__ deAtt,
                     float* __restrict__ attnOut)
{
    __shared__ float sQ[BHB][SEQ * QS];
    __shared__ float sK[BHB][SEQ * QS];
    __shared__ float sV[BHB][SEQ * VS];
    __shared__ float sS[BHB][SEQ * WS];
    __shared__ float sInv[BHB][SEQ];

    const int tid = threadIdx.x;
    const long bh0 = (long)blockIdx.x * BHB;

    // ---- Stage Q,K,V tiles into smem (float4 global loads, coalesced) ----
    for (int i = tid; i < BHB * (SEQ * DK / 4); i += THREADS) {
        int b  = i / (SEQ * DK / 4);
        int j  = i % (SEQ * DK / 4);
        int row = j / (DK / 4);
        int c4  = j % (DK / 4);
        const long base = (bh0 + b) * (long)(SEQ * DK);
        float4 q = ((const float4*)(Qg + base))[j];
        float4 k = ((const float4*)(Kg + base))[j];
        float4 v = ((const float4*)(Vg + base))[j];
        float* dq = &sQ[b][row * QS + 4 * c4];
        dq[0] = q.x; dq[1] = q.y; dq[2] = q.z; dq[3] = q.w;
        float* dk = &sK[b][row * QS + 4 * c4];
        dk[0] = k.x; dk[1] = k.y; dk[2] = k.z; dk[3] = k.w;
        *((float4*)(&sV[b][row * VS + 4 * c4])) = v;
    }
    __syncthreads();

    // ---- Phase A: S = Q K^T, 4x4 register tiles (25 tiles per bh) ----
    if (tid < BHB * 25) {
        int b    = tid / 25;
        int tile = tid % 25;
        int q0 = (tile / 5) * 4;
        int k0 = (tile % 5) * 4;
        float acc[4][4] = {};
        #pragma unroll 8
        for (int d = 0; d < DK; d++) {
            float qv[4], kv[4];
            #pragma unroll
            for (int i = 0; i < 4; i++) qv[i] = sQ[b][(q0 + i) * QS + d];
            #pragma unroll
            for (int j = 0; j < 4; j++) kv[j] = sK[b][(k0 + j) * QS + d];
            #pragma unroll
            for (int i = 0; i < 4; i++)
                #pragma unroll
                for (int j = 0; j < 4; j++)
                    acc[i][j] = fmaf(qv[i], kv[j], acc[i][j]);
        }
        #pragma unroll
        for (int i = 0; i < 4; i++)
            #pragma unroll
            for (int j = 0; j < 4; j++)
                sS[b][(q0 + i) * WS + (k0 + j)] = acc[i][j];
    }
    __syncthreads();

    // ---- exp(scale * S) * mask (mask read coalesced from global) ----
    for (int e = tid; e < BHB * SEQ * SEQ; e += THREADS) {
        int b = e / (SEQ * SEQ);
        int j = e % (SEQ * SEQ);
        int q = j / SEQ, k = j % SEQ;
        float raw = sS[b][q * WS + k];
        sS[b][q * WS + k] = __expf(raw * 0.125f) * Mg[(bh0 + b) * (long)(SEQ * SEQ) + j];
    }
    __syncthreads();

    // ---- row sums -> reciprocal ----
    if (tid < BHB * SEQ) {
        int b = tid / SEQ, q = tid % SEQ;
        float s = 0.f;
        #pragma unroll
        for (int k = 0; k < SEQ; k++) s += sS[b][q * WS + k];
        sInv[b][q] = 1.0f / (s + 1e-8f);
    }
    __syncthreads();

    // ---- normalize -> write attn; form W = attn - |q-k| in place ----
    for (int e = tid; e < BHB * SEQ * SEQ; e += THREADS) {
        int b = e / (SEQ * SEQ);
        int j = e % (SEQ * SEQ);
        int q = j / SEQ, k = j % SEQ;
        float a = sS[b][q * WS + k] * sInv[b][q];
        attnOut[(bh0 + b) * (long)(SEQ * SEQ) + j] = a;
        sS[b][q * WS + k] = a - fabsf((float)(q - k));
    }
    __syncthreads();

    // ---- Phase C: deAtt = W @ V, 4q x 4d register tiles (80 tiles per bh) ----
    if (tid < BHB * 80) {
        int b    = tid / 80;
        int tile = tid % 80;
        int q0 = (tile / 16) * 4;
        int d0 = (tile % 16) * 4;
        float4 acc[4];
        #pragma unroll
        for (int i = 0; i < 4; i++) acc[i] = make_float4(0.f, 0.f, 0.f, 0.f);
        #pragma unroll
        for (int k = 0; k < SEQ; k++) {
            float4 v = *((const float4*)(&sV[b][k * VS + d0]));
            #pragma unroll
            for (int i = 0; i < 4; i++) {
                float w = sS[b][(q0 + i) * WS + k];
                acc[i].x = fmaf(w, v.x, acc[i].x);
                acc[i].y = fmaf(w, v.y, acc[i].y);
                acc[i].z = fmaf(w, v.z, acc[i].z);
                acc[i].w = fmaf(w, v.w, acc[i].w);
            }
        }
        const long base = (bh0 + b) * (long)(SEQ * DK);
        #pragma unroll
        for (int i = 0; i < 4; i++)
            *((float4*)(deAtt + base + (q0 + i) * DK + d0)) = acc[i];
    }
}

extern "C" void kernel_launch(void* const* d_in, const int* in_sizes, int n_in,
                              void* d_out, int out_size)
{
    const float* Q = (const float*)d_in[0];
    const float* K = (const float*)d_in[1];
    const float* V = (const float*)d_in[2];
    const float* M = (const float*)d_in[3];

    // number of (b,h) problems
    const int bh = in_sizes[0] / (SEQ * DK);   // 512*16 = 8192

    float* deAtt   = (float*)d_out;                       // [bh, SEQ, DK]
    float* attnOut = (float*)d_out + (long)in_sizes[0];   // [bh, SEQ, SEQ]

    const int grid = bh / BHB;
    sdpa_rel_kernel<<<grid, THREADS>>>(Q, K, V, M, deAtt, attnOut);
}